// round 5
// baseline (speedup 1.0000x reference)
#include <cuda_runtime.h>
#include <cstdint>

// Problem constants
#define NN   50000
#define EE   800000
#define NIN  128
#define NHID 256

#define SCAN_B  1024
#define SCAN_NB ((NN + SCAN_B - 1) / SCAN_B)   // 49

// ---------------- scratch (no allocations allowed) ----------------
__device__ int   g_is64;
__device__ int   g_deg[NN];
__device__ float g_dinv[NN];
__device__ int   g_ptr[NN + 1];
__device__ int   g_cur[NN];
__device__ int   g_src[EE];
__device__ int   g_bsum[SCAN_NB];
__device__ float g_h[(size_t)NN * NIN];    // aggregated features

// ---------------- prep: init degree + detect edge dtype ----------------
__global__ void k_prep(const void* __restrict__ ei) {
    int i = blockIdx.x * blockDim.x + threadIdx.x;
    if (i < NN) g_deg[i] = 1;   // self loop
    if (i == 0) {
        const long long* p = (const long long*)ei;
        int ok = 1;
        #pragma unroll
        for (int t = 0; t < 16; t++) {
            long long v = p[t];
            ok &= (v >= 0 && v < NN) ? 1 : 0;
        }
        g_is64 = ok;
    }
}

// ---------------- degree count (4 edges / thread) ----------------
__global__ void k_count(const void* __restrict__ ei) {
    int e4 = 4 * (blockIdx.x * blockDim.x + threadIdx.x);
    if (e4 >= EE) return;
    int c0, c1, c2, c3;
    if (g_is64) {
        const longlong2* p = (const longlong2*)((const long long*)ei + EE + e4);
        longlong2 a = p[0], b = p[1];
        c0 = (int)a.x; c1 = (int)a.y; c2 = (int)b.x; c3 = (int)b.y;
    } else {
        int4 v = *(const int4*)((const int*)ei + EE + e4);
        c0 = v.x; c1 = v.y; c2 = v.z; c3 = v.w;
    }
    atomicAdd(&g_deg[c0], 1);
    atomicAdd(&g_deg[c1], 1);
    atomicAdd(&g_deg[c2], 1);
    atomicAdd(&g_deg[c3], 1);
}

// ---------------- scan1: block-scan of (deg-1), also computes dinv ----------------
__global__ void k_scan1() {
    __shared__ int sh[SCAN_B];
    int gid = blockIdx.x * SCAN_B + threadIdx.x;
    int d = (gid < NN) ? g_deg[gid] : 1;
    int v = d - 1;
    if (gid < NN) g_dinv[gid] = rsqrtf((float)d);
    sh[threadIdx.x] = v;
    __syncthreads();
    for (int off = 1; off < SCAN_B; off <<= 1) {
        int t = (threadIdx.x >= off) ? sh[threadIdx.x - off] : 0;
        __syncthreads();
        sh[threadIdx.x] += t;
        __syncthreads();
    }
    if (gid < NN) g_ptr[gid] = sh[threadIdx.x] - v;   // exclusive within block
    if (threadIdx.x == SCAN_B - 1) g_bsum[blockIdx.x] = sh[SCAN_B - 1];
}

__global__ void k_scan2() {
    __shared__ int sh[64];
    int t = threadIdx.x;
    sh[t] = (t < SCAN_NB) ? g_bsum[t] : 0;
    __syncthreads();
    if (t < SCAN_NB) {
        int acc = 0;
        #pragma unroll
        for (int b = 0; b < SCAN_NB; b++)
            if (b < t) acc += sh[b];
        g_bsum[t] = acc;
    }
}

__global__ void k_scan3() {
    int gid = blockIdx.x * SCAN_B + threadIdx.x;
    if (gid < NN) {
        int p = g_ptr[gid] + g_bsum[blockIdx.x];
        g_ptr[gid] = p;
        g_cur[gid] = p;
    }
    if (gid == 0) g_ptr[NN] = EE;
}

// ---------------- fill CSR (4 edges / thread) ----------------
__global__ void k_fill(const void* __restrict__ ei) {
    int e4 = 4 * (blockIdx.x * blockDim.x + threadIdx.x);
    if (e4 >= EE) return;
    int r0, r1, r2, r3, c0, c1, c2, c3;
    if (g_is64) {
        const longlong2* pr = (const longlong2*)((const long long*)ei + e4);
        const longlong2* pc = (const longlong2*)((const long long*)ei + EE + e4);
        longlong2 a = pr[0], b = pr[1], c = pc[0], d = pc[1];
        r0 = (int)a.x; r1 = (int)a.y; r2 = (int)b.x; r3 = (int)b.y;
        c0 = (int)c.x; c1 = (int)c.y; c2 = (int)d.x; c3 = (int)d.y;
    } else {
        int4 a = *(const int4*)((const int*)ei + e4);
        int4 b = *(const int4*)((const int*)ei + EE + e4);
        r0 = a.x; r1 = a.y; r2 = a.z; r3 = a.w;
        c0 = b.x; c1 = b.y; c2 = b.z; c3 = b.w;
    }
    g_src[atomicAdd(&g_cur[c0], 1)] = r0;
    g_src[atomicAdd(&g_cur[c1], 1)] = r1;
    g_src[atomicAdd(&g_cur[c2], 1)] = r2;
    g_src[atomicAdd(&g_cur[c3], 1)] = r3;
}

// ---------------- aggregation: warp per target node, gather-only ----------------
__global__ void __launch_bounds__(256) k_agg(const float* __restrict__ x) {
    int w = (blockIdx.x * blockDim.x + threadIdx.x) >> 5;
    int lane = threadIdx.x & 31;
    if (w >= NN) return;
    float di = g_dinv[w];
    const float4* __restrict__ x4 = (const float4*)x;
    float4 a = x4[(size_t)w * 32 + lane];           // self loop
    a.x *= di; a.y *= di; a.z *= di; a.w *= di;
    int s = g_ptr[w], e = g_ptr[w + 1];
    #pragma unroll 2
    for (int k = s; k < e; k++) {
        int   j  = __ldg(&g_src[k]);
        float wj = __ldg(&g_dinv[j]);
        float4 v = x4[(size_t)j * 32 + lane];
        a.x = fmaf(wj, v.x, a.x);
        a.y = fmaf(wj, v.y, a.y);
        a.z = fmaf(wj, v.z, a.z);
        a.w = fmaf(wj, v.w, a.w);
    }
    a.x *= di; a.y *= di; a.z *= di; a.w *= di;
    ((float4*)g_h)[(size_t)w * 32 + lane] = a;
}

// ---------------- fused two-layer TF32 tensor-core GEMM ----------------
// One block per 128-row tile:
//   phase 1: h1s[128,256] = tf32(relu(g_h_tile[128,128] @ W0))   (SMEM resident)
//   phase 2: out[128,256] = relu(h1s @ W1)
#define ASTRIDE 132   // full A tile [128 rows][128 k], pad: bank (4r+c)%32 unique
#define HSTRIDE 260   // h1s [128 rows][256 k], 260%32=4 -> same conflict-free pattern
#define BSTRIDE 136   // Bs [32 k][128 n], 136%32=8 -> bank (8k+n)%32 unique

#define AS_ELE (128 * ASTRIDE)
#define H1_ELE (128 * HSTRIDE)
#define BS_ELE (32 * BSTRIDE)
#define SMEM_BYTES ((AS_ELE + H1_ELE + BS_ELE) * 4)

__device__ __forceinline__ uint32_t f2tf32(float x) {
    uint32_t u;
    asm("cvt.rna.tf32.f32 %0, %1;" : "=r"(u) : "f"(x));
    return u;
}

__device__ __forceinline__ void mma_tf32(float& d0, float& d1, float& d2, float& d3,
                                         uint32_t a0, uint32_t a1, uint32_t a2, uint32_t a3,
                                         uint32_t b0, uint32_t b1) {
    asm volatile(
        "mma.sync.aligned.m16n8k8.row.col.f32.tf32.tf32.f32 "
        "{%0,%1,%2,%3}, {%4,%5,%6,%7}, {%8,%9}, {%0,%1,%2,%3};"
        : "+f"(d0), "+f"(d1), "+f"(d2), "+f"(d3)
        : "r"(a0), "r"(a1), "r"(a2), "r"(a3), "r"(b0), "r"(b1));
}

// 32-wide k-slab of mma for one warp; A operand from smem (stride templated)
template<int AST>
__device__ __forceinline__ void mma_slab(const uint32_t* __restrict__ Asm,
                                         const uint32_t* __restrict__ Bs,
                                         int wM, int wN, int r4, int c4, int kbase,
                                         float acc[4][4][4]) {
    #pragma unroll
    for (int kk = 0; kk < 32; kk += 8) {
        uint32_t af[4][4];
        #pragma unroll
        for (int mt = 0; mt < 4; mt++) {
            int r = wM + mt * 16 + r4;
            int c = kbase + kk + c4;
            af[mt][0] = Asm[r * AST + c];
            af[mt][1] = Asm[(r + 8) * AST + c];
            af[mt][2] = Asm[r * AST + c + 4];
            af[mt][3] = Asm[(r + 8) * AST + c + 4];
        }
        uint32_t bf[4][2];
        #pragma unroll
        for (int nt = 0; nt < 4; nt++) {
            int n = wN + nt * 8 + r4;
            int k = kk + c4;
            bf[nt][0] = Bs[k * BSTRIDE + n];
            bf[nt][1] = Bs[(k + 4) * BSTRIDE + n];
        }
        #pragma unroll
        for (int mt = 0; mt < 4; mt++)
            #pragma unroll
            for (int nt = 0; nt < 4; nt++)
                mma_tf32(acc[mt][nt][0], acc[mt][nt][1], acc[mt][nt][2], acc[mt][nt][3],
                         af[mt][0], af[mt][1], af[mt][2], af[mt][3],
                         bf[nt][0], bf[nt][1]);
    }
}

__global__ void __launch_bounds__(256) gemm_fused(const float* __restrict__ W0,
                                                  const float* __restrict__ W1,
                                                  float* __restrict__ Cout, int M) {
    extern __shared__ uint32_t smem[];
    uint32_t* As = smem;                    // full A tile, tf32
    uint32_t* H1 = smem + AS_ELE;           // relu(h@W0), tf32
    uint32_t* Bs = smem + AS_ELE + H1_ELE;  // 32x128 weight slab

    int tid  = threadIdx.x;
    int lane = tid & 31;
    int wid  = tid >> 5;
    int wM = (wid >> 2) * 64;
    int wN = (wid & 3) * 32;
    int r4 = lane >> 2;
    int c4 = lane & 3;
    int brow = blockIdx.x * 128;

    // ---- load full A tile (128 x 128 fp32 -> tf32) ----
    #pragma unroll
    for (int t = 0; t < 16; t++) {
        int idx = tid + t * 256;             // float4 index; 32 per row
        int row = idx >> 5;
        int col = (idx & 31) * 4;
        int grow = brow + row;
        float4 v = make_float4(0.f, 0.f, 0.f, 0.f);
        if (grow < M) v = *(const float4*)(g_h + (size_t)grow * NIN + col);
        uint32_t* dst = &As[row * ASTRIDE + col];
        dst[0] = f2tf32(v.x); dst[1] = f2tf32(v.y);
        dst[2] = f2tf32(v.z); dst[3] = f2tf32(v.w);
    }
    __syncthreads();

    float acc[4][4][4];

    // ---- phase 1: h1s = tf32(relu(A @ W0)), both 128-col halves ----
    #pragma unroll
    for (int nh = 0; nh < 2; nh++) {
        int bcol = nh * 128;
        #pragma unroll
        for (int mt = 0; mt < 4; mt++)
            #pragma unroll
            for (int nt = 0; nt < 4; nt++)
                #pragma unroll
                for (int r = 0; r < 4; r++) acc[mt][nt][r] = 0.f;

        for (int k0 = 0; k0 < NIN; k0 += 32) {
            // load Bs: W0[k0..k0+31][bcol..bcol+127]
            #pragma unroll
            for (int t = 0; t < 4; t++) {
                int idx = tid + t * 256;
                int row = idx >> 5;
                int col = (idx & 31) * 4;
                float4 v = *(const float4*)(W0 + (size_t)(k0 + row) * NHID + bcol + col);
                uint32_t* dst = &Bs[row * BSTRIDE + col];
                dst[0] = f2tf32(v.x); dst[1] = f2tf32(v.y);
                dst[2] = f2tf32(v.z); dst[3] = f2tf32(v.w);
            }
            __syncthreads();
            mma_slab<ASTRIDE>(As, Bs, wM, wN, r4, c4, k0, acc);
            __syncthreads();
        }

        // epilogue -> H1 (relu + tf32), uint2 stores (col even, 8B aligned)
        #pragma unroll
        for (int mt = 0; mt < 4; mt++) {
            int row0 = wM + mt * 16 + r4;
            #pragma unroll
            for (int nt = 0; nt < 4; nt++) {
                int col = bcol + wN + nt * 8 + c4 * 2;
                uint2 v0, v1;
                v0.x = f2tf32(fmaxf(acc[mt][nt][0], 0.f));
                v0.y = f2tf32(fmaxf(acc[mt][nt][1], 0.f));
                v1.x = f2tf32(fmaxf(acc[mt][nt][2], 0.f));
                v1.y = f2tf32(fmaxf(acc[mt][nt][3], 0.f));
                *(uint2*)&H1[row0 * HSTRIDE + col] = v0;
                *(uint2*)&H1[(row0 + 8) * HSTRIDE + col] = v1;
            }
        }
    }

    // ---- phase 2: out = relu(H1 @ W1) ----
    #pragma unroll
    for (int nh = 0; nh < 2; nh++) {
        int bcol = nh * 128;
        #pragma unroll
        for (int mt = 0; mt < 4; mt++)
            #pragma unroll
            for (int nt = 0; nt < 4; nt++)
                #pragma unroll
                for (int r = 0; r < 4; r++) acc[mt][nt][r] = 0.f;

        for (int k0 = 0; k0 < NHID; k0 += 32) {
            #pragma unroll
            for (int t = 0; t < 4; t++) {
                int idx = tid + t * 256;
                int row = idx >> 5;
                int col = (idx & 31) * 4;
                float4 v = *(const float4*)(W1 + (size_t)(k0 + row) * NHID + bcol + col);
                uint32_t* dst = &Bs[row * BSTRIDE + col];
                dst[0] = f2tf32(v.x); dst[1] = f2tf32(v.y);
                dst[2] = f2tf32(v.z); dst[3] = f2tf32(v.w);
            }
            __syncthreads();   // also orders H1 writes before first read
            mma_slab<HSTRIDE>(H1, Bs, wM, wN, r4, c4, k0, acc);
            __syncthreads();
        }

        // epilogue -> global, relu, float2
        #pragma unroll
        for (int mt = 0; mt < 4; mt++) {
            int row0 = brow + wM + mt * 16 + r4;
            #pragma unroll
            for (int nt = 0; nt < 4; nt++) {
                int col = bcol + wN + nt * 8 + c4 * 2;
                if (row0 < M) {
                    float2 v;
                    v.x = fmaxf(acc[mt][nt][0], 0.f);
                    v.y = fmaxf(acc[mt][nt][1], 0.f);
                    *(float2*)(Cout + (size_t)row0 * NHID + col) = v;
                }
                if (row0 + 8 < M) {
                    float2 v;
                    v.x = fmaxf(acc[mt][nt][2], 0.f);
                    v.y = fmaxf(acc[mt][nt][3], 0.f);
                    *(float2*)(Cout + (size_t)(row0 + 8) * NHID + col) = v;
                }
            }
        }
    }
}

extern "C" void kernel_launch(void* const* d_in, const int* in_sizes, int n_in,
                              void* d_out, int out_size) {
    const float* x  = nullptr;
    const float* W0 = nullptr;
    const float* W1 = nullptr;
    const void*  ei = nullptr;
    for (int i = 0; i < n_in; i++) {
        long long sz = in_sizes[i];
        if      (sz == (long long)NN * NIN)    x  = (const float*)d_in[i];
        else if (sz == (long long)NIN * NHID)  W0 = (const float*)d_in[i];
        else if (sz == (long long)NHID * NHID) W1 = (const float*)d_in[i];
        else if (sz == (long long)2 * EE)      ei = d_in[i];
    }

    // Idempotent, capture-safe (not a stream op), no static guard.
    cudaFuncSetAttribute(gemm_fused, cudaFuncAttributeMaxDynamicSharedMemorySize,
                         SMEM_BYTES);

    k_prep <<<(NN + 255) / 256, 256>>>(ei);
    k_count<<<(EE / 4 + 255) / 256, 256>>>(ei);
    k_scan1<<<SCAN_NB, SCAN_B>>>();
    k_scan2<<<1, 64>>>();
    k_scan3<<<SCAN_NB, SCAN_B>>>();
    k_fill <<<(EE / 4 + 255) / 256, 256>>>(ei);

    k_agg<<<(NN * 32 + 255) / 256, 256>>>(x);

    int nblk = (NN + 127) / 128;   // 391
    gemm_fused<<<nblk, 256, SMEM_BYTES>>>(W0, W1, (float*)d_out, NN);
}

// round 6
// speedup vs baseline: 1.0158x; 1.0158x over previous
#include <cuda_runtime.h>
#include <cuda_fp16.h>
#include <cstdint>

// Problem constants
#define NN   50000
#define EE   800000
#define NIN  128
#define NHID 256

#define SCAN_B  1024
#define SCAN_NB ((NN + SCAN_B - 1) / SCAN_B)   // 49
#define XV4     (NN * NIN / 4)                 // 1.6M float4 in x

// ---------------- scratch (no allocations allowed) ----------------
__device__ int    g_is64;
__device__ int    g_deg[NN];
__device__ float  g_dinv[NN];
__device__ int    g_ptr[NN + 1];
__device__ int    g_cur[NN];
__device__ int    g_src[EE];
__device__ int    g_bsum[SCAN_NB];
__device__ __half g_xh[(size_t)NN * NIN];   // x converted to fp16
__device__ float  g_h [(size_t)NN * NIN];   // aggregated features
__device__ float  g_h1[(size_t)NN * NHID];  // after layer 1

// ---------------- prep: init degree + detect edge dtype + convert x->fp16 ----------------
__global__ void k_prep(const float* __restrict__ x, const void* __restrict__ ei) {
    int i = blockIdx.x * blockDim.x + threadIdx.x;
    if (i < NN) g_deg[i] = 1;   // self loop
    if (i == 0) {
        const long long* p = (const long long*)ei;
        int ok = 1;
        #pragma unroll
        for (int t = 0; t < 16; t++) {
            long long v = p[t];
            ok &= (v >= 0 && v < NN) ? 1 : 0;
        }
        g_is64 = ok;
    }
    if (i < XV4) {
        float4 v = ((const float4*)x)[i];
        __half2 h0 = __floats2half2_rn(v.x, v.y);
        __half2 h1 = __floats2half2_rn(v.z, v.w);
        uint2 u;
        u.x = *(uint32_t*)&h0;
        u.y = *(uint32_t*)&h1;
        ((uint2*)g_xh)[i] = u;
    }
}

// ---------------- degree count (4 edges / thread) ----------------
__global__ void k_count(const void* __restrict__ ei) {
    int e4 = 4 * (blockIdx.x * blockDim.x + threadIdx.x);
    if (e4 >= EE) return;
    int c0, c1, c2, c3;
    if (g_is64) {
        const longlong2* p = (const longlong2*)((const long long*)ei + EE + e4);
        longlong2 a = p[0], b = p[1];
        c0 = (int)a.x; c1 = (int)a.y; c2 = (int)b.x; c3 = (int)b.y;
    } else {
        int4 v = *(const int4*)((const int*)ei + EE + e4);
        c0 = v.x; c1 = v.y; c2 = v.z; c3 = v.w;
    }
    atomicAdd(&g_deg[c0], 1);
    atomicAdd(&g_deg[c1], 1);
    atomicAdd(&g_deg[c2], 1);
    atomicAdd(&g_deg[c3], 1);
}

// ---------------- scan1: block-scan of (deg-1), also computes dinv ----------------
__global__ void k_scan1() {
    __shared__ int sh[SCAN_B];
    int gid = blockIdx.x * SCAN_B + threadIdx.x;
    int d = (gid < NN) ? g_deg[gid] : 1;
    int v = d - 1;
    if (gid < NN) g_dinv[gid] = rsqrtf((float)d);
    sh[threadIdx.x] = v;
    __syncthreads();
    for (int off = 1; off < SCAN_B; off <<= 1) {
        int t = (threadIdx.x >= off) ? sh[threadIdx.x - off] : 0;
        __syncthreads();
        sh[threadIdx.x] += t;
        __syncthreads();
    }
    if (gid < NN) g_ptr[gid] = sh[threadIdx.x] - v;   // exclusive within block
    if (threadIdx.x == SCAN_B - 1) g_bsum[blockIdx.x] = sh[SCAN_B - 1];
}

// scan3: each block computes its own prefix over g_bsum (49 entries) inline
__global__ void k_scan3() {
    __shared__ int sh[64];
    __shared__ int s_off;
    int t = threadIdx.x;
    if (t < 64) sh[t] = (t < SCAN_NB && t < blockIdx.x) ? g_bsum[t] : 0;
    __syncthreads();
    if (t == 0) {
        int acc = 0;
        #pragma unroll
        for (int b = 0; b < 64; b++) acc += sh[b];
        s_off = acc;
    }
    __syncthreads();
    int gid = blockIdx.x * SCAN_B + t;
    if (gid < NN) {
        int p = g_ptr[gid] + s_off;
        g_ptr[gid] = p;
        g_cur[gid] = p;
    }
    if (gid == 0) g_ptr[NN] = EE;
}

// ---------------- fill CSR (4 edges / thread) ----------------
__global__ void k_fill(const void* __restrict__ ei) {
    int e4 = 4 * (blockIdx.x * blockDim.x + threadIdx.x);
    if (e4 >= EE) return;
    int r0, r1, r2, r3, c0, c1, c2, c3;
    if (g_is64) {
        const longlong2* pr = (const longlong2*)((const long long*)ei + e4);
        const longlong2* pc = (const longlong2*)((const long long*)ei + EE + e4);
        longlong2 a = pr[0], b = pr[1], c = pc[0], d = pc[1];
        r0 = (int)a.x; r1 = (int)a.y; r2 = (int)b.x; r3 = (int)b.y;
        c0 = (int)c.x; c1 = (int)c.y; c2 = (int)d.x; c3 = (int)d.y;
    } else {
        int4 a = *(const int4*)((const int*)ei + e4);
        int4 b = *(const int4*)((const int*)ei + EE + e4);
        r0 = a.x; r1 = a.y; r2 = a.z; r3 = a.w;
        c0 = b.x; c1 = b.y; c2 = b.z; c3 = b.w;
    }
    g_src[atomicAdd(&g_cur[c0], 1)] = r0;
    g_src[atomicAdd(&g_cur[c1], 1)] = r1;
    g_src[atomicAdd(&g_cur[c2], 1)] = r2;
    g_src[atomicAdd(&g_cur[c3], 1)] = r3;
}

// ---------------- aggregation: warp per target node, fp16 gather ----------------
// Each lane handles 4 features (one uint2 = 2 x half2); warp covers 128 features.
__global__ void __launch_bounds__(256) k_agg() {
    int w = (blockIdx.x * blockDim.x + threadIdx.x) >> 5;
    int lane = threadIdx.x & 31;
    if (w >= NN) return;
    float di = g_dinv[w];
    const uint2* __restrict__ xh = (const uint2*)g_xh;   // 32 uint2 per row

    uint2 raw = xh[(size_t)w * 32 + lane];               // self loop
    float2 s0 = __half22float2(*(const __half2*)&raw.x);
    float2 s1 = __half22float2(*(const __half2*)&raw.y);
    float4 a;
    a.x = di * s0.x; a.y = di * s0.y; a.z = di * s1.x; a.w = di * s1.y;

    int s = g_ptr[w], e = g_ptr[w + 1];
    #pragma unroll 2
    for (int k = s; k < e; k++) {
        int   j  = __ldg(&g_src[k]);
        float wj = __ldg(&g_dinv[j]);
        uint2 r  = xh[(size_t)j * 32 + lane];
        float2 v0 = __half22float2(*(const __half2*)&r.x);
        float2 v1 = __half22float2(*(const __half2*)&r.y);
        a.x = fmaf(wj, v0.x, a.x);
        a.y = fmaf(wj, v0.y, a.y);
        a.z = fmaf(wj, v1.x, a.z);
        a.w = fmaf(wj, v1.y, a.w);
    }
    a.x *= di; a.y *= di; a.z *= di; a.w *= di;
    ((float4*)g_h)[(size_t)w * 32 + lane] = a;
}

// ---------------- TF32 tensor-core GEMM + ReLU (unfused, R2 config) ----------------
#define GBM 128
#define GBN 128
#define GBK 32
#define ASTR 36     // As row stride: banks (4r + c) mod 32 unique
#define BSTR 136    // Bs row stride: banks (8k + n) mod 32 unique

__device__ __forceinline__ uint32_t f2tf32(float x) {
    uint32_t u;
    asm("cvt.rna.tf32.f32 %0, %1;" : "=r"(u) : "f"(x));
    return u;
}

__device__ __forceinline__ void mma_tf32(float& d0, float& d1, float& d2, float& d3,
                                         uint32_t a0, uint32_t a1, uint32_t a2, uint32_t a3,
                                         uint32_t b0, uint32_t b1) {
    asm volatile(
        "mma.sync.aligned.m16n8k8.row.col.f32.tf32.tf32.f32 "
        "{%0,%1,%2,%3}, {%4,%5,%6,%7}, {%8,%9}, {%0,%1,%2,%3};"
        : "+f"(d0), "+f"(d1), "+f"(d2), "+f"(d3)
        : "r"(a0), "r"(a1), "r"(a2), "r"(a3), "r"(b0), "r"(b1));
}

// LAYER 1: A = g_h (K=128),  C = g_h1
// LAYER 2: A = g_h1 (K=256), C = Cout (d_out)
template<int K, int LAYER>
__global__ void __launch_bounds__(256) gemm_tc(const float* __restrict__ B,
                                               float* __restrict__ Cout, int M) {
    const float* __restrict__ A = (LAYER == 1) ? g_h : g_h1;
    float* __restrict__ C = (LAYER == 1) ? g_h1 : Cout;

    __shared__ uint32_t As[GBM * ASTR];   // [row][k]
    __shared__ uint32_t Bs[GBK * BSTR];   // [k][n]

    int tid  = threadIdx.x;
    int lane = tid & 31;
    int wid  = tid >> 5;
    int wM = (wid >> 2) * 64;
    int wN = (wid & 3) * 32;

    int brow = blockIdx.x * GBM;
    int bcol = blockIdx.y * GBN;

    float acc[4][4][4];
    #pragma unroll
    for (int mt = 0; mt < 4; mt++)
        #pragma unroll
        for (int nt = 0; nt < 4; nt++)
            #pragma unroll
            for (int r = 0; r < 4; r++) acc[mt][nt][r] = 0.f;

    int r4 = lane >> 2;
    int c4 = lane & 3;

    for (int k0 = 0; k0 < K; k0 += GBK) {
        #pragma unroll
        for (int t = 0; t < 4; t++) {
            int idx  = tid + t * 256;
            int row  = idx >> 3;
            int col  = (idx & 7) * 4;
            int grow = brow + row;
            float4 v = make_float4(0.f, 0.f, 0.f, 0.f);
            if (grow < M) v = *(const float4*)(A + (size_t)grow * K + k0 + col);
            uint32_t* dst = &As[row * ASTR + col];
            dst[0] = f2tf32(v.x); dst[1] = f2tf32(v.y);
            dst[2] = f2tf32(v.z); dst[3] = f2tf32(v.w);
        }
        #pragma unroll
        for (int t = 0; t < 4; t++) {
            int idx = tid + t * 256;
            int row = idx >> 5;
            int col = (idx & 31) * 4;
            float4 v = *(const float4*)(B + (size_t)(k0 + row) * NHID + bcol + col);
            uint32_t* dst = &Bs[row * BSTR + col];
            dst[0] = f2tf32(v.x); dst[1] = f2tf32(v.y);
            dst[2] = f2tf32(v.z); dst[3] = f2tf32(v.w);
        }
        __syncthreads();

        #pragma unroll
        for (int kk = 0; kk < GBK; kk += 8) {
            uint32_t af[4][4];
            #pragma unroll
            for (int mt = 0; mt < 4; mt++) {
                int r = wM + mt * 16 + r4;
                int c = kk + c4;
                af[mt][0] = As[r * ASTR + c];
                af[mt][1] = As[(r + 8) * ASTR + c];
                af[mt][2] = As[r * ASTR + c + 4];
                af[mt][3] = As[(r + 8) * ASTR + c + 4];
            }
            uint32_t bf[4][2];
            #pragma unroll
            for (int nt = 0; nt < 4; nt++) {
                int n = wN + nt * 8 + r4;
                int k = kk + c4;
                bf[nt][0] = Bs[k * BSTR + n];
                bf[nt][1] = Bs[(k + 4) * BSTR + n];
            }
            #pragma unroll
            for (int mt = 0; mt < 4; mt++)
                #pragma unroll
                for (int nt = 0; nt < 4; nt++)
                    mma_tf32(acc[mt][nt][0], acc[mt][nt][1], acc[mt][nt][2], acc[mt][nt][3],
                             af[mt][0], af[mt][1], af[mt][2], af[mt][3],
                             bf[nt][0], bf[nt][1]);
        }
        __syncthreads();
    }

    #pragma unroll
    for (int mt = 0; mt < 4; mt++) {
        int row0 = brow + wM + mt * 16 + r4;
        #pragma unroll
        for (int nt = 0; nt < 4; nt++) {
            int col = bcol + wN + nt * 8 + c4 * 2;
            if (row0 < M) {
                float2 v;
                v.x = fmaxf(acc[mt][nt][0], 0.f);
                v.y = fmaxf(acc[mt][nt][1], 0.f);
                *(float2*)(C + (size_t)row0 * NHID + col) = v;
            }
            if (row0 + 8 < M) {
                float2 v;
                v.x = fmaxf(acc[mt][nt][2], 0.f);
                v.y = fmaxf(acc[mt][nt][3], 0.f);
                *(float2*)(C + (size_t)(row0 + 8) * NHID + col) = v;
            }
        }
    }
}

extern "C" void kernel_launch(void* const* d_in, const int* in_sizes, int n_in,
                              void* d_out, int out_size) {
    const float* x  = nullptr;
    const float* W0 = nullptr;
    const float* W1 = nullptr;
    const void*  ei = nullptr;
    for (int i = 0; i < n_in; i++) {
        long long sz = in_sizes[i];
        if      (sz == (long long)NN * NIN)    x  = (const float*)d_in[i];
        else if (sz == (long long)NIN * NHID)  W0 = (const float*)d_in[i];
        else if (sz == (long long)NHID * NHID) W1 = (const float*)d_in[i];
        else if (sz == (long long)2 * EE)      ei = d_in[i];
    }

    k_prep <<<(XV4 + 255) / 256, 256>>>(x, ei);
    k_count<<<(EE / 4 + 255) / 256, 256>>>(ei);
    k_scan1<<<SCAN_NB, SCAN_B>>>();
    k_scan3<<<SCAN_NB, SCAN_B>>>();
    k_fill <<<(EE / 4 + 255) / 256, 256>>>(ei);

    k_agg<<<(NN * 32 + 255) / 256, 256>>>();

    dim3 gg((NN + GBM - 1) / GBM, NHID / GBN);
    gemm_tc<NIN,  1><<<gg, 256>>>(W0, nullptr, NN);        // g_h  @ W0 -> g_h1
    gemm_tc<NHID, 2><<<gg, 256>>>(W1, (float*)d_out, NN);  // g_h1 @ W1 -> out
}

// round 7
// speedup vs baseline: 1.3058x; 1.2855x over previous
#include <cuda_runtime.h>
#include <cuda_fp16.h>
#include <cstdint>

// Problem constants
#define NN   50000
#define EE   800000
#define NIN  128
#define NHID 256

#define SCAN_B  1024
#define SCAN_NB ((NN + SCAN_B - 1) / SCAN_B)   // 49
#define XV4     (NN * NIN / 4)                 // 1.6M float4 in x

// ---------------- scratch (no allocations allowed) ----------------
__device__ int    g_is64;
__device__ int    g_deg[NN];
__device__ float  g_dinv[NN];
__device__ int    g_ptr[NN + 1];
__device__ int    g_cur[NN];
__device__ int    g_src[EE];
__device__ int    g_bsum[SCAN_NB];
__device__ __half g_xh [(size_t)NN * NIN];    // x in fp16 (agg input)
__device__ __half g_hh [(size_t)NN * NIN];    // aggregated features, fp16
__device__ __half g_h1h[(size_t)NN * NHID];   // hidden layer, fp16
__device__ __half g_w0t[NHID * NIN];          // W0^T [n][k] fp16
__device__ __half g_w1t[NHID * NHID];         // W1^T [n][k] fp16

// ---------------- prep: deg init + dtype detect + x->fp16 + W transpose ----------------
__global__ void k_prep(const float* __restrict__ x, const void* __restrict__ ei,
                       const float* __restrict__ W0, const float* __restrict__ W1) {
    int i = blockIdx.x * blockDim.x + threadIdx.x;
    if (i < NN) g_deg[i] = 1;   // self loop
    if (i == 0) {
        const long long* p = (const long long*)ei;
        int ok = 1;
        #pragma unroll
        for (int t = 0; t < 16; t++) {
            long long v = p[t];
            ok &= (v >= 0 && v < NN) ? 1 : 0;
        }
        g_is64 = ok;
    }
    if (i < XV4) {
        float4 v = ((const float4*)x)[i];
        __half2 h0 = __floats2half2_rn(v.x, v.y);
        __half2 h1 = __floats2half2_rn(v.z, v.w);
        uint2 u;
        u.x = *(uint32_t*)&h0;
        u.y = *(uint32_t*)&h1;
        ((uint2*)g_xh)[i] = u;
    }
    if (i < NHID * NIN) {           // W0^T: i = n*128 + k
        int n = i >> 7, k = i & 127;
        g_w0t[i] = __float2half_rn(W0[k * NHID + n]);
    }
    if (i < NHID * NHID) {          // W1^T: i = n*256 + k
        int n = i >> 8, k = i & 255;
        g_w1t[i] = __float2half_rn(W1[k * NHID + n]);
    }
}

// ---------------- degree count (4 edges / thread) ----------------
__global__ void k_count(const void* __restrict__ ei) {
    int e4 = 4 * (blockIdx.x * blockDim.x + threadIdx.x);
    if (e4 >= EE) return;
    int c0, c1, c2, c3;
    if (g_is64) {
        const longlong2* p = (const longlong2*)((const long long*)ei + EE + e4);
        longlong2 a = p[0], b = p[1];
        c0 = (int)a.x; c1 = (int)a.y; c2 = (int)b.x; c3 = (int)b.y;
    } else {
        int4 v = *(const int4*)((const int*)ei + EE + e4);
        c0 = v.x; c1 = v.y; c2 = v.z; c3 = v.w;
    }
    atomicAdd(&g_deg[c0], 1);
    atomicAdd(&g_deg[c1], 1);
    atomicAdd(&g_deg[c2], 1);
    atomicAdd(&g_deg[c3], 1);
}

// ---------------- scan1: block-scan of (deg-1), also computes dinv ----------------
__global__ void k_scan1() {
    __shared__ int sh[SCAN_B];
    int gid = blockIdx.x * SCAN_B + threadIdx.x;
    int d = (gid < NN) ? g_deg[gid] : 1;
    int v = d - 1;
    if (gid < NN) g_dinv[gid] = rsqrtf((float)d);
    sh[threadIdx.x] = v;
    __syncthreads();
    for (int off = 1; off < SCAN_B; off <<= 1) {
        int t = (threadIdx.x >= off) ? sh[threadIdx.x - off] : 0;
        __syncthreads();
        sh[threadIdx.x] += t;
        __syncthreads();
    }
    if (gid < NN) g_ptr[gid] = sh[threadIdx.x] - v;   // exclusive within block
    if (threadIdx.x == SCAN_B - 1) g_bsum[blockIdx.x] = sh[SCAN_B - 1];
}

// scan3: each block sums its predecessor block-sums inline
__global__ void k_scan3() {
    __shared__ int sh[64];
    __shared__ int s_off;
    int t = threadIdx.x;
    if (t < 64) sh[t] = (t < SCAN_NB && t < blockIdx.x) ? g_bsum[t] : 0;
    __syncthreads();
    if (t == 0) {
        int acc = 0;
        #pragma unroll
        for (int b = 0; b < 64; b++) acc += sh[b];
        s_off = acc;
    }
    __syncthreads();
    int gid = blockIdx.x * SCAN_B + t;
    if (gid < NN) {
        int p = g_ptr[gid] + s_off;
        g_ptr[gid] = p;
        g_cur[gid] = p;
    }
    if (gid == 0) g_ptr[NN] = EE;
}

// ---------------- fill CSR (4 edges / thread) ----------------
__global__ void k_fill(const void* __restrict__ ei) {
    int e4 = 4 * (blockIdx.x * blockDim.x + threadIdx.x);
    if (e4 >= EE) return;
    int r0, r1, r2, r3, c0, c1, c2, c3;
    if (g_is64) {
        const longlong2* pr = (const longlong2*)((const long long*)ei + e4);
        const longlong2* pc = (const longlong2*)((const long long*)ei + EE + e4);
        longlong2 a = pr[0], b = pr[1], c = pc[0], d = pc[1];
        r0 = (int)a.x; r1 = (int)a.y; r2 = (int)b.x; r3 = (int)b.y;
        c0 = (int)c.x; c1 = (int)c.y; c2 = (int)d.x; c3 = (int)d.y;
    } else {
        int4 a = *(const int4*)((const int*)ei + e4);
        int4 b = *(const int4*)((const int*)ei + EE + e4);
        r0 = a.x; r1 = a.y; r2 = a.z; r3 = a.w;
        c0 = b.x; c1 = b.y; c2 = b.z; c3 = b.w;
    }
    g_src[atomicAdd(&g_cur[c0], 1)] = r0;
    g_src[atomicAdd(&g_cur[c1], 1)] = r1;
    g_src[atomicAdd(&g_cur[c2], 1)] = r2;
    g_src[atomicAdd(&g_cur[c3], 1)] = r3;
}

// ---------------- aggregation: warp per target node, fp16 in, fp16 out ----------------
__global__ void __launch_bounds__(256) k_agg() {
    int w = (blockIdx.x * blockDim.x + threadIdx.x) >> 5;
    int lane = threadIdx.x & 31;
    if (w >= NN) return;
    float di = g_dinv[w];
    const uint2* __restrict__ xh = (const uint2*)g_xh;   // 32 uint2 per row

    uint2 raw = xh[(size_t)w * 32 + lane];               // self loop
    float2 s0 = __half22float2(*(const __half2*)&raw.x);
    float2 s1 = __half22float2(*(const __half2*)&raw.y);
    float4 a;
    a.x = di * s0.x; a.y = di * s0.y; a.z = di * s1.x; a.w = di * s1.y;

    int s = g_ptr[w], e = g_ptr[w + 1];
    #pragma unroll 2
    for (int k = s; k < e; k++) {
        int   j  = __ldg(&g_src[k]);
        float wj = __ldg(&g_dinv[j]);
        uint2 r  = xh[(size_t)j * 32 + lane];
        float2 v0 = __half22float2(*(const __half2*)&r.x);
        float2 v1 = __half22float2(*(const __half2*)&r.y);
        a.x = fmaf(wj, v0.x, a.x);
        a.y = fmaf(wj, v0.y, a.y);
        a.z = fmaf(wj, v1.x, a.z);
        a.w = fmaf(wj, v1.y, a.w);
    }
    a.x *= di; a.y *= di; a.z *= di; a.w *= di;
    __half2 o0 = __floats2half2_rn(a.x, a.y);
    __half2 o1 = __floats2half2_rn(a.z, a.w);
    uint2 u;
    u.x = *(uint32_t*)&o0;
    u.y = *(uint32_t*)&o1;
    ((uint2*)g_hh)[(size_t)w * 32 + lane] = u;
}

// ---------------- FP16 tensor-core GEMM + ReLU ----------------
// C[M,256] = relu(A[M,K] @ W)   with W supplied transposed WT[n][k], all fp16.
// Block tile 128x128, K-slab 64. 8 warps (2M x 4N), warp tile 64x32.
// mma.sync.aligned.m16n8k16.row.col.f32.f16.f16.f32
#define AST 36   // smem row stride in 32-bit words (32 data + 4 pad); bank=4*r4+c4

__device__ __forceinline__ void mma_fp16(float& d0, float& d1, float& d2, float& d3,
                                         uint32_t a0, uint32_t a1, uint32_t a2, uint32_t a3,
                                         uint32_t b0, uint32_t b1) {
    asm volatile(
        "mma.sync.aligned.m16n8k16.row.col.f32.f16.f16.f32 "
        "{%0,%1,%2,%3}, {%4,%5,%6,%7}, {%8,%9}, {%0,%1,%2,%3};"
        : "+f"(d0), "+f"(d1), "+f"(d2), "+f"(d3)
        : "r"(a0), "r"(a1), "r"(a2), "r"(a3), "r"(b0), "r"(b1));
}

// LAYER 1: A = g_hh (K=128), WT = g_w0t, C = g_h1h (fp16)
// LAYER 2: A = g_h1h (K=256), WT = g_w1t, C = Cout (fp32)
template<int K, int LAYER>
__global__ void __launch_bounds__(256) gemm_fp16(float* __restrict__ Cout, int M) {
    const __half* __restrict__ A  = (LAYER == 1) ? g_hh : g_h1h;
    const __half* __restrict__ WT = (LAYER == 1) ? g_w0t : g_w1t;

    __shared__ uint32_t As[128 * AST];   // [row][k-words]
    __shared__ uint32_t Bs[128 * AST];   // [n][k-words]

    int tid  = threadIdx.x;
    int lane = tid & 31;
    int wid  = tid >> 5;
    int wM = (wid >> 2) * 64;
    int wN = (wid & 3) * 32;
    int r4 = lane >> 2;
    int c4 = lane & 3;

    int brow = blockIdx.x * 128;
    int bcol = blockIdx.y * 128;

    float acc[4][4][4];
    #pragma unroll
    for (int mt = 0; mt < 4; mt++)
        #pragma unroll
        for (int nt = 0; nt < 4; nt++)
            #pragma unroll
            for (int r = 0; r < 4; r++) acc[mt][nt][r] = 0.f;

    for (int k0 = 0; k0 < K; k0 += 64) {
        // A tile: 128 rows x 64 halves = 2048 uint2; 8 per thread
        #pragma unroll
        for (int t = 0; t < 8; t++) {
            int idx = tid + t * 256;
            int row = idx >> 4;            // 16 uint2 per row-slab
            int c   = idx & 15;
            uint2 v = make_uint2(0u, 0u);
            int grow = brow + row;
            if (grow < M)
                v = ((const uint2*)(A + (size_t)grow * K))[(k0 >> 2) + c];
            *(uint2*)&As[row * AST + c * 2] = v;
        }
        // B tile: 128 n-rows x 64 halves from WT
        #pragma unroll
        for (int t = 0; t < 8; t++) {
            int idx = tid + t * 256;
            int row = idx >> 4;
            int c   = idx & 15;
            uint2 v = ((const uint2*)(WT + (size_t)(bcol + row) * K))[(k0 >> 2) + c];
            *(uint2*)&Bs[row * AST + c * 2] = v;
        }
        __syncthreads();

        #pragma unroll
        for (int s = 0; s < 4; s++) {      // 4 x k16 steps
            int kw = s * 8;
            uint32_t af[4][4];
            #pragma unroll
            for (int mt = 0; mt < 4; mt++) {
                int r = wM + mt * 16 + r4;
                af[mt][0] = As[r * AST + c4 + kw];
                af[mt][1] = As[(r + 8) * AST + c4 + kw];
                af[mt][2] = As[r * AST + c4 + 4 + kw];
                af[mt][3] = As[(r + 8) * AST + c4 + 4 + kw];
            }
            uint32_t bf[4][2];
            #pragma unroll
            for (int nt = 0; nt < 4; nt++) {
                int n = wN + nt * 8 + r4;
                bf[nt][0] = Bs[n * AST + c4 + kw];
                bf[nt][1] = Bs[n * AST + c4 + 4 + kw];
            }
            #pragma unroll
            for (int mt = 0; mt < 4; mt++)
                #pragma unroll
                for (int nt = 0; nt < 4; nt++)
                    mma_fp16(acc[mt][nt][0], acc[mt][nt][1], acc[mt][nt][2], acc[mt][nt][3],
                             af[mt][0], af[mt][1], af[mt][2], af[mt][3],
                             bf[nt][0], bf[nt][1]);
        }
        __syncthreads();
    }

    // epilogue
    #pragma unroll
    for (int mt = 0; mt < 4; mt++) {
        int row0 = brow + wM + mt * 16 + r4;
        #pragma unroll
        for (int nt = 0; nt < 4; nt++) {
            int col = bcol + wN + nt * 8 + c4 * 2;
            if (LAYER == 1) {
                if (row0 < M) {
                    __half2 h = __floats2half2_rn(fmaxf(acc[mt][nt][0], 0.f),
                                                  fmaxf(acc[mt][nt][1], 0.f));
                    *(__half2*)(g_h1h + (size_t)row0 * NHID + col) = h;
                }
                if (row0 + 8 < M) {
                    __half2 h = __floats2half2_rn(fmaxf(acc[mt][nt][2], 0.f),
                                                  fmaxf(acc[mt][nt][3], 0.f));
                    *(__half2*)(g_h1h + (size_t)(row0 + 8) * NHID + col) = h;
                }
            } else {
                if (row0 < M) {
                    float2 v;
                    v.x = fmaxf(acc[mt][nt][0], 0.f);
                    v.y = fmaxf(acc[mt][nt][1], 0.f);
                    *(float2*)(Cout + (size_t)row0 * NHID + col) = v;
                }
                if (row0 + 8 < M) {
                    float2 v;
                    v.x = fmaxf(acc[mt][nt][2], 0.f);
                    v.y = fmaxf(acc[mt][nt][3], 0.f);
                    *(float2*)(Cout + (size_t)(row0 + 8) * NHID + col) = v;
                }
            }
        }
    }
}

extern "C" void kernel_launch(void* const* d_in, const int* in_sizes, int n_in,
                              void* d_out, int out_size) {
    const float* x  = nullptr;
    const float* W0 = nullptr;
    const float* W1 = nullptr;
    const void*  ei = nullptr;
    for (int i = 0; i < n_in; i++) {
        long long sz = in_sizes[i];
        if      (sz == (long long)NN * NIN)    x  = (const float*)d_in[i];
        else if (sz == (long long)NIN * NHID)  W0 = (const float*)d_in[i];
        else if (sz == (long long)NHID * NHID) W1 = (const float*)d_in[i];
        else if (sz == (long long)2 * EE)      ei = d_in[i];
    }

    k_prep <<<(XV4 + 255) / 256, 256>>>(x, ei, W0, W1);
    k_count<<<(EE / 4 + 255) / 256, 256>>>(ei);
    k_scan1<<<SCAN_NB, SCAN_B>>>();
    k_scan3<<<SCAN_NB, SCAN_B>>>();
    k_fill <<<(EE / 4 + 255) / 256, 256>>>(ei);

    k_agg<<<(NN * 32 + 255) / 256, 256>>>();

    dim3 gg((NN + 127) / 128, NHID / 128);
    gemm_fp16<NIN,  1><<<gg, 256>>>(nullptr, NN);          // g_hh @ W0 -> g_h1h
    gemm_fp16<NHID, 2><<<gg, 256>>>((float*)d_out, NN);    // g_h1h @ W1 -> out
}